// round 8
// baseline (speedup 1.0000x reference)
#include <cuda_runtime.h>
#include <cuda_bf16.h>

// RowSoftmax: out[e] = et[e] / segsum(et)[row[e]],  et = exp(leaky_relu(attr, 0.01))
// E = 33554432 edges, N = 1000000 nodes. edge_index is int32 on device.
//
// Measured structural floors (B300):
//   accum:     REDG spread-addr rate, ~1.29 cyc/lane/SM -> ~163us
//   normalize: 1 L1tex wavefront per random 4B gather   -> ~139us
// Flat 4-edges/thread is optimal (8/thread and grid-stride both regressed).
// Zero pass = capturable memset node. This round: TPB 256 -> 128 on hot
// kernels (halves per-CTA front-batched LDG count -> lower cross-CTA
// L1tex-queue spread), everything else identical to the 305.6us config.

#define N_NODES 1000000

__device__ float g_rowsum[N_NODES];

__device__ __forceinline__ float et_of(float x) {
    float l = (x > 0.0f) ? x : 0.01f * x;
    return __expf(l);
}

// Pass B: accumulate et into rowsum via L2 atomics (REDG). 4 edges/thread.
// Streaming loads use .cs (evict-first) so the 4MB rowsum stays L2-resident.
__global__ void __launch_bounds__(128)
accum_kernel(const int* __restrict__ row,
             const float* __restrict__ attr,
             int nvec, int E) {
    int i = blockIdx.x * blockDim.x + threadIdx.x;
    if (i < nvec) {
        int4   r = __ldcs(reinterpret_cast<const int4*>(row) + i);
        float4 a = __ldcs(reinterpret_cast<const float4*>(attr) + i);
        atomicAdd(&g_rowsum[r.x], et_of(a.x));
        atomicAdd(&g_rowsum[r.y], et_of(a.y));
        atomicAdd(&g_rowsum[r.z], et_of(a.z));
        atomicAdd(&g_rowsum[r.w], et_of(a.w));
    }
    // scalar tail (empty for E = 2^25)
    if (i == 0) {
        for (int e = nvec * 4; e < E; e++)
            atomicAdd(&g_rowsum[row[e]], et_of(attr[e]));
    }
}

// Pass C: out[e] = et[e] / rowsum[row[e]]. Division folded in (MUFU idle).
__global__ void __launch_bounds__(128)
normalize_kernel(const int* __restrict__ row,
                 const float* __restrict__ attr,
                 float* __restrict__ out,
                 int nvec, int E) {
    int i = blockIdx.x * blockDim.x + threadIdx.x;
    if (i < nvec) {
        int4   r = __ldcs(reinterpret_cast<const int4*>(row) + i);
        float4 a = __ldcs(reinterpret_cast<const float4*>(attr) + i);
        float s0 = g_rowsum[r.x];
        float s1 = g_rowsum[r.y];
        float s2 = g_rowsum[r.z];
        float s3 = g_rowsum[r.w];
        float4 o;
        o.x = __fdividef(et_of(a.x), s0);
        o.y = __fdividef(et_of(a.y), s1);
        o.z = __fdividef(et_of(a.z), s2);
        o.w = __fdividef(et_of(a.w), s3);
        __stcs(reinterpret_cast<float4*>(out) + i, o);
    }
    if (i == 0) {
        for (int e = nvec * 4; e < E; e++)
            out[e] = __fdividef(et_of(attr[e]), g_rowsum[row[e]]);
    }
}

extern "C" void kernel_launch(void* const* d_in, const int* in_sizes, int n_in,
                              void* d_out, int out_size) {
    // Inputs: edge_index int32 [2, E], edge_attr float32 [E], N (scalar)
    const int*   edge_index = (const int*)d_in[0];
    const float* edge_attr  = (const float*)d_in[1];
    const int E = in_sizes[1];
    const int* row = edge_index;   // edge_index[0] = first E entries

    float* out = (float*)d_out;

    const int nvec = E / 4;
    const int TPB = 128;

    // Zero rowsum via a capturable memset node (no allocation, no kernel).
    void* rowsum_ptr = nullptr;
    cudaGetSymbolAddress(&rowsum_ptr, g_rowsum);
    cudaMemsetAsync(rowsum_ptr, 0, N_NODES * sizeof(float), 0);

    accum_kernel<<<(nvec + TPB - 1) / TPB, TPB>>>(row, edge_attr, nvec, E);
    normalize_kernel<<<(nvec + TPB - 1) / TPB, TPB>>>(row, edge_attr, out, nvec, E);
}